// round 12
// baseline (speedup 1.0000x reference)
#include <cuda_runtime.h>
#include <cstdint>

// Problem constants
#define BB 2
#define SS 2048
#define DD 1024
#define HH 16
#define HD 64
#define MM (BB * SS)          // 4096 rows
#define ATTN_SCALE 0.125f     // 1/sqrt(64)

// ---------------------------------------------------------------------------
// Scratch (device globals; no runtime allocation allowed)
// ---------------------------------------------------------------------------
__device__ float g_qr[MM * DD];    // tf32-rounded q
__device__ float g_kr[MM * DD];
__device__ float g_vr[MM * DD];
__device__ float g_wq[DD * DD];    // tf32-rounded weights
__device__ float g_wk[DD * DD];
__device__ float g_wv[DD * DD];
__device__ float g_wo[DD * DD];
__device__ float g_qp[MM * DD];    // projections (pre-rounded, Q pre-scaled)
__device__ float g_kp[MM * DD];
__device__ float g_vp[MM * DD];
__device__ float g_att[MM * DD];   // attention out (pre-rounded)

// ---------------------------------------------------------------------------
// Helpers
// ---------------------------------------------------------------------------
__device__ __forceinline__ float tf32r(float x) {
    uint32_t u;
    asm("cvt.rna.tf32.f32 %0, %1;" : "=r"(u) : "f"(x));
    return __uint_as_float(u);
}

__device__ __forceinline__ void mma_tf32(float* d, const uint32_t* a, const uint32_t* b) {
    asm volatile(
        "mma.sync.aligned.m16n8k8.row.col.f32.tf32.tf32.f32 "
        "{%0,%1,%2,%3}, {%4,%5,%6,%7}, {%8,%9}, {%0,%1,%2,%3};\n"
        : "+f"(d[0]), "+f"(d[1]), "+f"(d[2]), "+f"(d[3])
        : "r"(a[0]), "r"(a[1]), "r"(a[2]), "r"(a[3]),
          "r"(b[0]), "r"(b[1]));
}

__device__ __forceinline__ void cp_async16(uint32_t smem_dst, const void* gmem_src) {
    asm volatile("cp.async.cg.shared.global [%0], [%1], 16;\n"
                 :: "r"(smem_dst), "l"(gmem_src));
}
__device__ __forceinline__ void cp_commit() {
    asm volatile("cp.async.commit_group;\n");
}
template <int N>
__device__ __forceinline__ void cp_wait() {
    asm volatile("cp.async.wait_group %0;\n" :: "n"(N));
}

__device__ __forceinline__ uint32_t smem_u32(const void* p) {
    uint32_t a;
    asm("{ .reg .u64 t; cvta.to.shared.u64 t, %1; cvt.u32.u64 %0, t; }"
        : "=r"(a) : "l"(p));
    return a;
}

#define MBAR_INIT(addr, cnt) \
    asm volatile("mbarrier.init.shared.b64 [%0], %1;" :: "r"(addr), "r"(cnt) : "memory")

__device__ __forceinline__ void mbar_wait(uint32_t addr, uint32_t parity) {
    asm volatile(
        "{\n\t.reg .pred P;\n\t"
        "W%=:\n\t"
        "mbarrier.try_wait.parity.acquire.cta.shared::cta.b64 P, [%0], %1, 0x989680;\n\t"
        "@P bra.uni D%=;\n\t"
        "bra.uni W%=;\n\t"
        "D%=:\n\t}"
        :: "r"(addr), "r"(parity) : "memory");
}

__device__ __forceinline__ void mbar_arrive(uint32_t addr) {
    asm volatile("mbarrier.arrive.shared.b64 _, [%0];" :: "r"(addr) : "memory");
}

// Arrive on mbar when all of this thread's prior cp.asyncs have completed.
__device__ __forceinline__ void cp_async_arrive(uint32_t addr) {
    asm volatile("cp.async.mbarrier.arrive.noinc.shared.b64 [%0];"
                 :: "r"(addr) : "memory");
}

// ---------------------------------------------------------------------------
// Single merged RNA-rounding pass for all 7 input tensors.
// ---------------------------------------------------------------------------
__global__ __launch_bounds__(256)
void round_all_kernel(const float4* __restrict__ q,  const float4* __restrict__ k,
                      const float4* __restrict__ v,  const float4* __restrict__ wq,
                      const float4* __restrict__ wk, const float4* __restrict__ wv,
                      const float4* __restrict__ wo,
                      float4* __restrict__ qr,  float4* __restrict__ kr,
                      float4* __restrict__ vr,  float4* __restrict__ wqr,
                      float4* __restrict__ wkr, float4* __restrict__ wvr,
                      float4* __restrict__ wor)
{
    int bid = blockIdx.x;
    const float4* src; float4* dst; int base;
    if      (bid < 1024) { src = q;  dst = qr;  base = bid;        }
    else if (bid < 2048) { src = k;  dst = kr;  base = bid - 1024; }
    else if (bid < 3072) { src = v;  dst = vr;  base = bid - 2048; }
    else if (bid < 3328) { src = wq; dst = wqr; base = bid - 3072; }
    else if (bid < 3584) { src = wk; dst = wkr; base = bid - 3328; }
    else if (bid < 3840) { src = wv; dst = wvr; base = bid - 3584; }
    else                 { src = wo; dst = wor; base = bid - 3840; }
    int i0 = base * 1024 + threadIdx.x;
#pragma unroll
    for (int u = 0; u < 4; u++) {
        int i = i0 + u * 256;
        float4 t = src[i];
        t.x = tf32r(t.x); t.y = tf32r(t.y);
        t.z = tf32r(t.z); t.w = tf32r(t.w);
        dst[i] = t;
    }
}

// ---------------------------------------------------------------------------
// mbarrier-pipelined tf32 GEMM (unchanged from R11 winner).
// ---------------------------------------------------------------------------
#define GST 20
#define GSTAGE (128 * GST)                 // floats per operand per stage
#define NST 4
#define BAR_BYTES 64                       // full[4] + empty[4]
#define GEMM_SMEM_BYTES (BAR_BYTES + NST * GSTAGE * 2 * 4)   // 81984

__device__ __forceinline__
void gemm_body(const float* __restrict__ A, const float* __restrict__ W,
               const float* __restrict__ bias, float* __restrict__ C,
               float scale, bool do_round)
{
    extern __shared__ char smg[];
    const uint32_t sb = smem_u32(smg);
    // full[s] at sb + s*8 ; empty[s] at sb + 32 + s*8
    float* As = (float*)(smg + BAR_BYTES);
    float* Ws = As + NST * GSTAGE;

    const int tid  = threadIdx.x;
    const int warp = tid >> 5;
    const int lane = tid & 31;
    const int g  = lane >> 2;
    const int t4 = lane & 3;
    const int wm = (warp & 1) * 64;
    const int wn = (warp >> 1) * 32;
    const int m0 = blockIdx.y << 7;
    const int n0 = blockIdx.x << 7;
    const int N = DD, K = DD;

    const int lr = tid >> 2;          // 0..63 (+64 for second row)
    const int lc = (tid & 3) << 2;    // 0,4,8,12

    if (tid == 0) {
#pragma unroll
        for (int s = 0; s < NST; s++) {
            MBAR_INIT(sb + s * 8, 256);        // full[s]
            MBAR_INIT(sb + 32 + s * 8, 256);   // empty[s]
        }
    }
    __syncthreads();   // barriers visible before any arrive

    const uint32_t as_b = (uint32_t)__cvta_generic_to_shared(As);
    const uint32_t ws_b = (uint32_t)__cvta_generic_to_shared(Ws);

    auto issue = [&](int kt) {
        int sbase = (kt & 3) * GSTAGE;
#pragma unroll
        for (int p = 0; p < 2; p++) {
            int row = lr + p * 64;
            cp_async16(as_b + (uint32_t)(sbase + row * GST + lc) * 4u,
                       A + (size_t)(m0 + row) * K + kt * 16 + lc);
            cp_async16(ws_b + (uint32_t)(sbase + row * GST + lc) * 4u,
                       W + (size_t)(n0 + row) * K + kt * 16 + lc);
        }
        cp_async_arrive(sb + (kt & 3) * 8);    // arrive full[s] on completion
    };

    issue(0);
    issue(1);
    issue(2);

    float acc[4][4][4];
#pragma unroll
    for (int mt = 0; mt < 4; mt++)
#pragma unroll
        for (int nt = 0; nt < 4; nt++)
#pragma unroll
            for (int c = 0; c < 4; c++) acc[mt][nt][c] = 0.f;

    const int KT = K >> 4;            // 64 slabs

    for (int kt = 0; kt < KT; kt++) {
        const int st = kt & 3;
        mbar_wait(sb + st * 8, (uint32_t)((kt >> 2) & 1));   // full[st]

        const float* Ab = As + st * GSTAGE;
        const float* Wb = Ws + st * GSTAGE;

#pragma unroll
        for (int ks = 0; ks < 2; ks++) {
            const int cb = ks * 8 + t4;
            uint32_t af[4][4];
#pragma unroll
            for (int mt = 0; mt < 4; mt++) {
                int rb = wm + mt * 16;
                af[mt][0] = __float_as_uint(Ab[(rb + g)     * GST + cb]);
                af[mt][1] = __float_as_uint(Ab[(rb + g + 8) * GST + cb]);
                af[mt][2] = __float_as_uint(Ab[(rb + g)     * GST + cb + 4]);
                af[mt][3] = __float_as_uint(Ab[(rb + g + 8) * GST + cb + 4]);
            }
            uint32_t bf[4][2];
#pragma unroll
            for (int nt = 0; nt < 4; nt++) {
                int rb = wn + nt * 8;
                bf[nt][0] = __float_as_uint(Wb[(rb + g) * GST + cb]);
                bf[nt][1] = __float_as_uint(Wb[(rb + g) * GST + cb + 4]);
            }
#pragma unroll
            for (int mt = 0; mt < 4; mt++)
#pragma unroll
                for (int nt = 0; nt < 4; nt++)
                    mma_tf32(acc[mt][nt], af[mt], bf[nt]);
        }

        mbar_arrive(sb + 32 + st * 8);        // empty[st]

        if (kt + 3 < KT) {
            if (kt >= 1)
                mbar_wait(sb + 32 + ((kt + 3) & 3) * 8,
                          (uint32_t)(((kt - 1) >> 2) & 1));
            issue(kt + 3);
        }
    }

    // epilogue
#pragma unroll
    for (int mt = 0; mt < 4; mt++) {
        int row0 = m0 + wm + mt * 16 + g;
#pragma unroll
        for (int nt = 0; nt < 4; nt++) {
            int col = n0 + wn + nt * 8 + t4 * 2;
            float b0 = bias[col], b1 = bias[col + 1];
            float v00 = acc[mt][nt][0] + b0, v01 = acc[mt][nt][1] + b1;
            float v10 = acc[mt][nt][2] + b0, v11 = acc[mt][nt][3] + b1;
            if (do_round) {
                v00 = tf32r(v00 * scale); v01 = tf32r(v01 * scale);
                v10 = tf32r(v10 * scale); v11 = tf32r(v11 * scale);
            }
            *(float2*)(C + (size_t)row0 * N + col)       = make_float2(v00, v01);
            *(float2*)(C + (size_t)(row0 + 8) * N + col) = make_float2(v10, v11);
        }
    }
}

// Q/K/V projections in one launch: blockIdx.z selects tensor.
__global__ __launch_bounds__(256, 2)
void gemm_qkv(const float* A0, const float* A1, const float* A2,
              const float* W0, const float* W1, const float* W2,
              const float* b0, const float* b1, const float* b2,
              float* C0, float* C1, float* C2)
{
    int z = blockIdx.z;
    const float* A = (z == 0) ? A0 : (z == 1) ? A1 : A2;
    const float* W = (z == 0) ? W0 : (z == 1) ? W1 : W2;
    const float* bi = (z == 0) ? b0 : (z == 1) ? b1 : b2;
    float* C = (z == 0) ? C0 : (z == 1) ? C1 : C2;
    gemm_body(A, W, bi, C, (z == 0) ? ATTN_SCALE : 1.0f, true);
}

// Output projection: raw fp32 result.
__global__ __launch_bounds__(256, 2)
void gemm_o(const float* __restrict__ A, const float* __restrict__ W,
            const float* __restrict__ bias, float* __restrict__ C)
{
    gemm_body(A, W, bias, C, 1.0f, false);
}

// ---------------------------------------------------------------------------
// Flash attention v5: mbarrier-decorrelated tiles + split K/V rings.
// BM=64, 4 warps, 1024 CTAs, 3 CTAs/SM.
// Per slot s in {0,1}: kf/ke/vf/ve mbarriers (count 128). Warps skew <= 2
// tiles; K(j+2) load overlaps softmax+PV of tile j; V(j+2) overlaps next QK.
// Compute per warp identical to R6/R11 -> bit-identical output.
// smem: 64B barriers + K[2][64][68] + V[2][64][72] = 71,744 B.
// ---------------------------------------------------------------------------
#define KST 68
#define VST 72
#define FB_BYTES 64
#define FLASH_SMEM_BYTES (FB_BYTES + (2 * 64 * KST + 2 * 64 * VST) * 4)

__global__ __launch_bounds__(128, 3)
void flash_tf32_pipe(const float* __restrict__ Q, const float* __restrict__ K,
                     const float* __restrict__ V, float* __restrict__ O)
{
    extern __shared__ char smfc[];
    const uint32_t sbf = smem_u32(smfc);
    // kf[s]=sbf+s*8, ke[s]=sbf+16+s*8, vf[s]=sbf+32+s*8, ve[s]=sbf+48+s*8
    float* Kb = (float*)(smfc + FB_BYTES);   // [2][64][68]
    float* Vb = Kb + 2 * 64 * KST;           // [2][64][72]

    const int tid  = threadIdx.x;
    const int warp = tid >> 5;
    const int lane = tid & 31;
    const int g  = lane >> 2;
    const int t4 = lane & 3;
    const int mrow = warp * 16;

    const int q0 = blockIdx.x << 6;
    const int h  = blockIdx.y;
    const int b  = blockIdx.z;

    const float* Qg = Q + ((size_t)(b * SS + q0)) * DD + h * HD;
    const float* Kg = K + ((size_t)b * SS) * DD + h * HD;
    const float* Vg = V + ((size_t)b * SS) * DD + h * HD;

    const uint32_t kb_b = (uint32_t)__cvta_generic_to_shared(Kb);
    const uint32_t vb_b = (uint32_t)__cvta_generic_to_shared(Vb);

    if (tid == 0) {
#pragma unroll
        for (int s = 0; s < 2; s++) {
            MBAR_INIT(sbf + s * 8, 128);        // kf
            MBAR_INIT(sbf + 16 + s * 8, 128);   // ke
            MBAR_INIT(sbf + 32 + s * 8, 128);   // vf
            MBAR_INIT(sbf + 48 + s * 8, 128);   // ve
        }
    }

    auto issue_k = [&](int j) {
        int s = j & 1;
#pragma unroll
        for (int p = 0; p < 8; p++) {
            int idx = tid + p * 128;
            int r  = idx >> 4;
            int c  = (idx & 15) << 2;
            cp_async16(kb_b + (uint32_t)(s * 64 * KST + r * KST + c) * 4u,
                       Kg + (size_t)(j * 64 + r) * DD + c);
        }
        cp_async_arrive(sbf + s * 8);           // kf[s]
    };
    auto issue_v = [&](int j) {
        int s = j & 1;
#pragma unroll
        for (int p = 0; p < 8; p++) {
            int idx = tid + p * 128;
            int r  = idx >> 4;
            int c  = (idx & 15) << 2;
            cp_async16(vb_b + (uint32_t)(s * 64 * VST + r * VST + c) * 4u,
                       Vg + (size_t)(j * 64 + r) * DD + c);
        }
        cp_async_arrive(sbf + 32 + s * 8);      // vf[s]
    };

    // Stage Q through K-buffer slot 0 (commit-group path), then registers.
#pragma unroll
    for (int p = 0; p < 8; p++) {
        int idx = tid + p * 128;
        int r  = idx >> 4;
        int c  = (idx & 15) << 2;
        cp_async16(kb_b + (uint32_t)(r * KST + c) * 4u,
                   Qg + (size_t)r * DD + c);
    }
    cp_commit();
    cp_wait<0>();
    __syncthreads();      // Q visible + mbarrier inits visible

    uint32_t qf[8][4];
#pragma unroll
    for (int ks = 0; ks < 8; ks++) {
        int cb = ks * 8 + t4;
        qf[ks][0] = __float_as_uint(Kb[(mrow + g)     * KST + cb]);
        qf[ks][1] = __float_as_uint(Kb[(mrow + g + 8) * KST + cb]);
        qf[ks][2] = __float_as_uint(Kb[(mrow + g)     * KST + cb + 4]);
        qf[ks][3] = __float_as_uint(Kb[(mrow + g + 8) * KST + cb + 4]);
    }
    __syncthreads();      // all warps done reading Q before K0 overwrites it

    issue_k(0); issue_v(0);
    issue_k(1); issue_v(1);

    float o_acc[8][4];
#pragma unroll
    for (int nt = 0; nt < 8; nt++)
#pragma unroll
        for (int c = 0; c < 4; c++) o_acc[nt][c] = 0.f;
    float m0r = -__int_as_float(0x7f800000);
    float m1r = -__int_as_float(0x7f800000);
    float l0r = 0.f, l1r = 0.f;

    const int srcA = (lane & 28) | (t4 >> 1);
    const int srcB = srcA + 2;
    const bool sel = (t4 & 1) != 0;
    const int NT = SS / 64;   // 32

    for (int j = 0; j < NT; j++) {
        const int s = j & 1;
        const uint32_t par = (uint32_t)((j >> 1) & 1);
        const float* Kt = Kb + s * 64 * KST;
        const float* Vt = Vb + s * 64 * VST;

        // ---- wait K full, S = Q K^T (K-frags double-buffered across ks) ----
        mbar_wait(sbf + s * 8, par);                     // kf[s]

        float sc[8][4];
#pragma unroll
        for (int nt = 0; nt < 8; nt++)
#pragma unroll
            for (int c = 0; c < 4; c++) sc[nt][c] = 0.f;

        uint32_t kfA[8][2], kfB[8][2];
        {
            const int cb0 = t4;
#pragma unroll
            for (int nt = 0; nt < 8; nt++) {
                kfA[nt][0] = __float_as_uint(Kt[(nt * 8 + g) * KST + cb0]);
                kfA[nt][1] = __float_as_uint(Kt[(nt * 8 + g) * KST + cb0 + 4]);
            }
        }
#pragma unroll
        for (int ks = 0; ks < 8; ks++) {
            uint32_t (*cur)[2] = (ks & 1) ? kfB : kfA;
            uint32_t (*nxt)[2] = (ks & 1) ? kfA : kfB;
            if (ks < 7) {
                const int cb = (ks + 1) * 8 + t4;
#pragma unroll
                for (int nt = 0; nt < 8; nt++) {
                    nxt[nt][0] = __float_as_uint(Kt[(nt * 8 + g) * KST + cb]);
                    nxt[nt][1] = __float_as_uint(Kt[(nt * 8 + g) * KST + cb + 4]);
                }
            }
#pragma unroll
            for (int nt = 0; nt < 8; nt++)
                mma_tf32(sc[nt], qf[ks], cur[nt]);
        }

        mbar_arrive(sbf + 16 + s * 8);                   // ke[s]: K reads done

        // ---- online softmax (no K/V smem access) ----
        float mx0 = sc[0][0], mx1 = sc[0][2];
#pragma unroll
        for (int nt = 0; nt < 8; nt++) {
            mx0 = fmaxf(mx0, fmaxf(sc[nt][0], sc[nt][1]));
            mx1 = fmaxf(mx1, fmaxf(sc[nt][2], sc[nt][3]));
        }
        mx0 = fmaxf(mx0, __shfl_xor_sync(0xffffffffu, mx0, 1));
        mx0 = fmaxf(mx0, __shfl_xor_sync(0xffffffffu, mx0, 2));
        mx1 = fmaxf(mx1, __shfl_xor_sync(0xffffffffu, mx1, 1));
        mx1 = fmaxf(mx1, __shfl_xor_sync(0xffffffffu, mx1, 2));

        float mn0 = fmaxf(m0r, mx0);
        float mn1 = fmaxf(m1r, mx1);
        float corr0 = __expf(m0r - mn0);
        float corr1 = __expf(m1r - mn1);
        m0r = mn0; m1r = mn1;

        float rs0 = 0.f, rs1 = 0.f;
#pragma unroll
        for (int nt = 0; nt < 8; nt++) {
            sc[nt][0] = __expf(sc[nt][0] - mn0);
            sc[nt][1] = __expf(sc[nt][1] - mn0);
            sc[nt][2] = __expf(sc[nt][2] - mn1);
            sc[nt][3] = __expf(sc[nt][3] - mn1);
            rs0 += sc[nt][0] + sc[nt][1];
            rs1 += sc[nt][2] + sc[nt][3];
        }
        rs0 += __shfl_xor_sync(0xffffffffu, rs0, 1);
        rs0 += __shfl_xor_sync(0xffffffffu, rs0, 2);
        rs1 += __shfl_xor_sync(0xffffffffu, rs1, 1);
        rs1 += __shfl_xor_sync(0xffffffffu, rs1, 2);
        l0r = l0r * corr0 + rs0;
        l1r = l1r * corr1 + rs1;

#pragma unroll
        for (int nt = 0; nt < 8; nt++) {
            o_acc[nt][0] *= corr0; o_acc[nt][1] *= corr0;
            o_acc[nt][2] *= corr1; o_acc[nt][3] *= corr1;
        }

        // ---- refill K slot s with tile j+2 (overlaps PV + next QK) ----
        if (j + 2 < NT) {
            mbar_wait(sbf + 16 + s * 8, par);            // ke[s] drained
            issue_k(j + 2);
        }

        // ---- wait V full, O += P V ----
        mbar_wait(sbf + 32 + s * 8, par);                // vf[s]

        auto build_af = [&](int ks, uint32_t af[4]) {
            float xA0 = __shfl_sync(0xffffffffu, sc[ks][0], srcA);
            float xA1 = __shfl_sync(0xffffffffu, sc[ks][1], srcA);
            float xA2 = __shfl_sync(0xffffffffu, sc[ks][2], srcA);
            float xA3 = __shfl_sync(0xffffffffu, sc[ks][3], srcA);
            float xB0 = __shfl_sync(0xffffffffu, sc[ks][0], srcB);
            float xB1 = __shfl_sync(0xffffffffu, sc[ks][1], srcB);
            float xB2 = __shfl_sync(0xffffffffu, sc[ks][2], srcB);
            float xB3 = __shfl_sync(0xffffffffu, sc[ks][3], srcB);
            af[0] = __float_as_uint(tf32r(sel ? xA1 : xA0));
            af[1] = __float_as_uint(tf32r(sel ? xA3 : xA2));
            af[2] = __float_as_uint(tf32r(sel ? xB1 : xB0));
            af[3] = __float_as_uint(tf32r(sel ? xB3 : xB2));
        };
        auto load_vf = [&](int ks, uint32_t vf[8][2]) {
#pragma unroll
            for (int nt = 0; nt < 8; nt++) {
                vf[nt][0] = __float_as_uint(Vt[(ks * 8 + t4)     * VST + nt * 8 + g]);
                vf[nt][1] = __float_as_uint(Vt[(ks * 8 + t4 + 4) * VST + nt * 8 + g]);
            }
        };

        uint32_t pfA[4], pfB[4], vfA[8][2], vfB[8][2];
        build_af(0, pfA);
        load_vf(0, vfA);
#pragma unroll
        for (int ks = 0; ks < 8; ks++) {
            uint32_t* pc = (ks & 1) ? pfB : pfA;
            uint32_t (*vc)[2] = (ks & 1) ? vfB : vfA;
            uint32_t* pn = (ks & 1) ? pfA : pfB;
            uint32_t (*vn)[2] = (ks & 1) ? vfA : vfB;
            if (ks < 7) {
                build_af(ks + 1, pn);
                load_vf(ks + 1, vn);
            }
#pragma unroll
            for (int nt = 0; nt < 8; nt++)
                mma_tf32(o_acc[nt], pc, vc[nt]);
        }

        mbar_arrive(sbf + 48 + s * 8);                   // ve[s]: V reads done

        // ---- refill V slot s with tile j+2 (overlaps next tile's QK) ----
        if (j + 2 < NT) {
            mbar_wait(sbf + 48 + s * 8, par);            // ve[s] drained
            issue_v(j + 2);
        }
    }

    // epilogue (pre-rounded for O-projection GEMM)
    float inv0 = 1.0f / l0r;
    float inv1 = 1.0f / l1r;
    int row0 = q0 + mrow + g;
#pragma unroll
    for (int nt = 0; nt < 8; nt++) {
        int col = h * HD + nt * 8 + t4 * 2;
        float2 v0 = make_float2(tf32r(o_acc[nt][0] * inv0), tf32r(o_acc[nt][1] * inv0));
        float2 v1 = make_float2(tf32r(o_acc[nt][2] * inv1), tf32r(o_acc[nt][3] * inv1));
        *(float2*)(O + ((size_t)(b * SS + row0)) * DD + col)     = v0;
        *(float2*)(O + ((size_t)(b * SS + row0 + 8)) * DD + col) = v1;
    }
}

// ---------------------------------------------------------------------------
// Launch
// ---------------------------------------------------------------------------
extern "C" void kernel_launch(void* const* d_in, const int* in_sizes, int n_in,
                              void* d_out, int out_size)
{
    const float* q  = (const float*)d_in[0];
    const float* k  = (const float*)d_in[1];
    const float* v  = (const float*)d_in[2];
    const float* Wq = (const float*)d_in[3];
    const float* bq = (const float*)d_in[4];
    const float* Wk = (const float*)d_in[5];
    const float* bk = (const float*)d_in[6];
    const float* Wv = (const float*)d_in[7];
    const float* bv = (const float*)d_in[8];
    const float* Wo = (const float*)d_in[9];
    const float* bo = (const float*)d_in[10];
    float* out = (float*)d_out;

    float *qr, *kr, *vr, *wq, *wk, *wv, *wo, *qp, *kp, *vp, *att;
    cudaGetSymbolAddress((void**)&qr,  g_qr);
    cudaGetSymbolAddress((void**)&kr,  g_kr);
    cudaGetSymbolAddress((void**)&vr,  g_vr);
    cudaGetSymbolAddress((void**)&wq,  g_wq);
    cudaGetSymbolAddress((void**)&wk,  g_wk);
    cudaGetSymbolAddress((void**)&wv,  g_wv);
    cudaGetSymbolAddress((void**)&wo,  g_wo);
    cudaGetSymbolAddress((void**)&qp,  g_qp);
    cudaGetSymbolAddress((void**)&kp,  g_kp);
    cudaGetSymbolAddress((void**)&vp,  g_vp);
    cudaGetSymbolAddress((void**)&att, g_att);

    cudaFuncSetAttribute(gemm_qkv, cudaFuncAttributeMaxDynamicSharedMemorySize, GEMM_SMEM_BYTES);
    cudaFuncSetAttribute(gemm_o,   cudaFuncAttributeMaxDynamicSharedMemorySize, GEMM_SMEM_BYTES);
    cudaFuncSetAttribute(flash_tf32_pipe, cudaFuncAttributeMaxDynamicSharedMemorySize, FLASH_SMEM_BYTES);

    // 1) RNA-round all inputs in one launch
    round_all_kernel<<<4096, 256>>>(
        (const float4*)q,  (const float4*)k,  (const float4*)v,
        (const float4*)Wq, (const float4*)Wk, (const float4*)Wv, (const float4*)Wo,
        (float4*)qr, (float4*)kr, (float4*)vr,
        (float4*)wq, (float4*)wk, (float4*)wv, (float4*)wo);

    // 2) Q/K/V projections in one launch (z selects; Q pre-scaled)
    dim3 qkv_grid(DD / 128, MM / 128, 3);   // (8, 32, 3)
    gemm_qkv<<<qkv_grid, 256, GEMM_SMEM_BYTES>>>(qr, kr, vr, wq, wk, wv,
                                                 bq, bk, bv, qp, kp, vp);

    // 3) Attention (BM=64: 1024 CTAs, 3 CTAs/SM)
    dim3 attn_grid(SS / 64, HH, BB);        // (32, 16, 2)
    flash_tf32_pipe<<<attn_grid, 128, FLASH_SMEM_BYTES>>>(qp, kp, vp, att);

    // 4) Output projection (raw fp32 result)
    dim3 gemm_grid(DD / 128, MM / 128);     // (8, 32)
    gemm_o<<<gemm_grid, 256, GEMM_SMEM_BYTES>>>(att, wo, bo, out);
}

// round 14
// speedup vs baseline: 1.0483x; 1.0483x over previous
#include <cuda_runtime.h>
#include <cstdint>

// Problem constants
#define BB 2
#define SS 2048
#define DD 1024
#define HH 16
#define HD 64
#define MM (BB * SS)          // 4096 rows
#define ATTN_SCALE 0.125f     // 1/sqrt(64)

// ---------------------------------------------------------------------------
// Scratch (device globals; no runtime allocation allowed)
// ---------------------------------------------------------------------------
__device__ float g_qp[MM * DD];    // projections (pre-rounded, Q pre-scaled)
__device__ float g_kp[MM * DD];
__device__ float g_vp[MM * DD];
__device__ float g_att[MM * DD];   // attention out (pre-rounded)

// ---------------------------------------------------------------------------
// Helpers
// ---------------------------------------------------------------------------
__device__ __forceinline__ float tf32r(float x) {
    uint32_t u;
    asm("cvt.rna.tf32.f32 %0, %1;" : "=r"(u) : "f"(x));
    return __uint_as_float(u);
}

__device__ __forceinline__ uint32_t tf32r_bits(float x) {
    uint32_t u;
    asm("cvt.rna.tf32.f32 %0, %1;" : "=r"(u) : "f"(x));
    return u;
}

__device__ __forceinline__ void mma_tf32(float* d, const uint32_t* a, const uint32_t* b) {
    asm volatile(
        "mma.sync.aligned.m16n8k8.row.col.f32.tf32.tf32.f32 "
        "{%0,%1,%2,%3}, {%4,%5,%6,%7}, {%8,%9}, {%0,%1,%2,%3};\n"
        : "+f"(d[0]), "+f"(d[1]), "+f"(d[2]), "+f"(d[3])
        : "r"(a[0]), "r"(a[1]), "r"(a[2]), "r"(a[3]),
          "r"(b[0]), "r"(b[1]));
}

__device__ __forceinline__ void cp_async16(uint32_t smem_dst, const void* gmem_src) {
    asm volatile("cp.async.cg.shared.global [%0], [%1], 16;\n"
                 :: "r"(smem_dst), "l"(gmem_src));
}
__device__ __forceinline__ void cp_commit() {
    asm volatile("cp.async.commit_group;\n");
}
template <int N>
__device__ __forceinline__ void cp_wait() {
    asm volatile("cp.async.wait_group %0;\n" :: "n"(N));
}

__device__ __forceinline__ uint32_t smem_u32(const void* p) {
    uint32_t a;
    asm("{ .reg .u64 t; cvta.to.shared.u64 t, %1; cvt.u32.u64 %0, t; }"
        : "=r"(a) : "l"(p));
    return a;
}

#define MBAR_INIT(addr, cnt) \
    asm volatile("mbarrier.init.shared.b64 [%0], %1;" :: "r"(addr), "r"(cnt) : "memory")

__device__ __forceinline__ void mbar_wait(uint32_t addr, uint32_t parity) {
    asm volatile(
        "{\n\t.reg .pred P;\n\t"
        "W%=:\n\t"
        "mbarrier.try_wait.parity.acquire.cta.shared::cta.b64 P, [%0], %1, 0x989680;\n\t"
        "@P bra.uni D%=;\n\t"
        "bra.uni W%=;\n\t"
        "D%=:\n\t}"
        :: "r"(addr), "r"(parity) : "memory");
}

__device__ __forceinline__ void mbar_arrive(uint32_t addr) {
    asm volatile("mbarrier.arrive.shared.b64 _, [%0];" :: "r"(addr) : "memory");
}

// Arrive on mbar when all of this thread's prior cp.asyncs have completed.
__device__ __forceinline__ void cp_async_arrive(uint32_t addr) {
    asm volatile("cp.async.mbarrier.arrive.noinc.shared.b64 [%0];"
                 :: "r"(addr) : "memory");
}

// ---------------------------------------------------------------------------
// mbarrier-pipelined tf32 GEMM (R11 winner) with in-loop fragment rounding:
// RA/RB select cvt.rna on A/B fragments after LDS (bit-identical to reading
// pre-rounded copies; eliminates the standalone rounding pass).
// ---------------------------------------------------------------------------
#define GST 20
#define GSTAGE (128 * GST)                 // floats per operand per stage
#define NST 4
#define BAR_BYTES 64                       // full[4] + empty[4]
#define GEMM_SMEM_BYTES (BAR_BYTES + NST * GSTAGE * 2 * 4)   // 81984

template <bool RA, bool RB>
__device__ __forceinline__
void gemm_body(const float* __restrict__ A, const float* __restrict__ W,
               const float* __restrict__ bias, float* __restrict__ C,
               float scale, bool do_round)
{
    extern __shared__ char smg[];
    const uint32_t sb = smem_u32(smg);
    // full[s] at sb + s*8 ; empty[s] at sb + 32 + s*8
    float* As = (float*)(smg + BAR_BYTES);
    float* Ws = As + NST * GSTAGE;

    const int tid  = threadIdx.x;
    const int warp = tid >> 5;
    const int lane = tid & 31;
    const int g  = lane >> 2;
    const int t4 = lane & 3;
    const int wm = (warp & 1) * 64;
    const int wn = (warp >> 1) * 32;
    const int m0 = blockIdx.y << 7;
    const int n0 = blockIdx.x << 7;
    const int N = DD, K = DD;

    const int lr = tid >> 2;          // 0..63 (+64 for second row)
    const int lc = (tid & 3) << 2;    // 0,4,8,12

    if (tid == 0) {
#pragma unroll
        for (int s = 0; s < NST; s++) {
            MBAR_INIT(sb + s * 8, 256);        // full[s]
            MBAR_INIT(sb + 32 + s * 8, 256);   // empty[s]
        }
    }
    __syncthreads();   // barriers visible before any arrive

    const uint32_t as_b = (uint32_t)__cvta_generic_to_shared(As);
    const uint32_t ws_b = (uint32_t)__cvta_generic_to_shared(Ws);

    auto issue = [&](int kt) {
        int sbase = (kt & 3) * GSTAGE;
#pragma unroll
        for (int p = 0; p < 2; p++) {
            int row = lr + p * 64;
            cp_async16(as_b + (uint32_t)(sbase + row * GST + lc) * 4u,
                       A + (size_t)(m0 + row) * K + kt * 16 + lc);
            cp_async16(ws_b + (uint32_t)(sbase + row * GST + lc) * 4u,
                       W + (size_t)(n0 + row) * K + kt * 16 + lc);
        }
        cp_async_arrive(sb + (kt & 3) * 8);    // arrive full[s] on completion
    };

    issue(0);
    issue(1);
    issue(2);

    float acc[4][4][4];
#pragma unroll
    for (int mt = 0; mt < 4; mt++)
#pragma unroll
        for (int nt = 0; nt < 4; nt++)
#pragma unroll
            for (int c = 0; c < 4; c++) acc[mt][nt][c] = 0.f;

    const int KT = K >> 4;            // 64 slabs

    for (int kt = 0; kt < KT; kt++) {
        const int st = kt & 3;
        mbar_wait(sb + st * 8, (uint32_t)((kt >> 2) & 1));   // full[st]

        const float* Ab = As + st * GSTAGE;
        const float* Wb = Ws + st * GSTAGE;

#pragma unroll
        for (int ks = 0; ks < 2; ks++) {
            const int cb = ks * 8 + t4;
            uint32_t af[4][4];
#pragma unroll
            for (int mt = 0; mt < 4; mt++) {
                int rb = wm + mt * 16;
                float a0 = Ab[(rb + g)     * GST + cb];
                float a1 = Ab[(rb + g + 8) * GST + cb];
                float a2 = Ab[(rb + g)     * GST + cb + 4];
                float a3 = Ab[(rb + g + 8) * GST + cb + 4];
                af[mt][0] = RA ? tf32r_bits(a0) : __float_as_uint(a0);
                af[mt][1] = RA ? tf32r_bits(a1) : __float_as_uint(a1);
                af[mt][2] = RA ? tf32r_bits(a2) : __float_as_uint(a2);
                af[mt][3] = RA ? tf32r_bits(a3) : __float_as_uint(a3);
            }
            uint32_t bf[4][2];
#pragma unroll
            for (int nt = 0; nt < 4; nt++) {
                int rb = wn + nt * 8;
                float b0 = Wb[(rb + g) * GST + cb];
                float b1 = Wb[(rb + g) * GST + cb + 4];
                bf[nt][0] = RB ? tf32r_bits(b0) : __float_as_uint(b0);
                bf[nt][1] = RB ? tf32r_bits(b1) : __float_as_uint(b1);
            }
#pragma unroll
            for (int mt = 0; mt < 4; mt++)
#pragma unroll
                for (int nt = 0; nt < 4; nt++)
                    mma_tf32(acc[mt][nt], af[mt], bf[nt]);
        }

        mbar_arrive(sb + 32 + st * 8);        // empty[st]

        if (kt + 3 < KT) {
            if (kt >= 1)
                mbar_wait(sb + 32 + ((kt + 3) & 3) * 8,
                          (uint32_t)(((kt - 1) >> 2) & 1));
            issue(kt + 3);
        }
    }

    // epilogue
#pragma unroll
    for (int mt = 0; mt < 4; mt++) {
        int row0 = m0 + wm + mt * 16 + g;
#pragma unroll
        for (int nt = 0; nt < 4; nt++) {
            int col = n0 + wn + nt * 8 + t4 * 2;
            float b0 = bias[col], b1 = bias[col + 1];
            float v00 = acc[mt][nt][0] + b0, v01 = acc[mt][nt][1] + b1;
            float v10 = acc[mt][nt][2] + b0, v11 = acc[mt][nt][3] + b1;
            if (do_round) {
                v00 = tf32r(v00 * scale); v01 = tf32r(v01 * scale);
                v10 = tf32r(v10 * scale); v11 = tf32r(v11 * scale);
            }
            *(float2*)(C + (size_t)row0 * N + col)       = make_float2(v00, v01);
            *(float2*)(C + (size_t)(row0 + 8) * N + col) = make_float2(v10, v11);
        }
    }
}

// Q/K/V projections in one launch (raw inputs; frags rounded in-loop).
__global__ __launch_bounds__(256, 2)
void gemm_qkv(const float* A0, const float* A1, const float* A2,
              const float* W0, const float* W1, const float* W2,
              const float* b0, const float* b1, const float* b2,
              float* C0, float* C1, float* C2)
{
    int z = blockIdx.z;
    const float* A = (z == 0) ? A0 : (z == 1) ? A1 : A2;
    const float* W = (z == 0) ? W0 : (z == 1) ? W1 : W2;
    const float* bi = (z == 0) ? b0 : (z == 1) ? b1 : b2;
    float* C = (z == 0) ? C0 : (z == 1) ? C1 : C2;
    gemm_body<true, true>(A, W, bi, C, (z == 0) ? ATTN_SCALE : 1.0f, true);
}

// Output projection: A=att pre-rounded (no cvt), W=Wo raw (cvt B-frags).
__global__ __launch_bounds__(256, 2)
void gemm_o(const float* __restrict__ A, const float* __restrict__ W,
            const float* __restrict__ bias, float* __restrict__ C)
{
    gemm_body<false, true>(A, W, bias, C, 1.0f, false);
}

// ---------------------------------------------------------------------------
// Flash attention (R11/R6-passing version, syncthreads turns):
// BM=64, 4 warps, 1024 CTAs, 3 CTAs/SM. Fragment double-buffering inside
// QK^T and PV loops. P via shfl+tf32r. smem: K[2][64][68]+V[2][64][72].
// ---------------------------------------------------------------------------
#define KST 68
#define VST 72
#define FLASH_SMEM_BYTES ((2 * 64 * KST + 2 * 64 * VST) * 4)

__global__ __launch_bounds__(128, 3)
void flash_tf32_pipe(const float* __restrict__ Q, const float* __restrict__ K,
                     const float* __restrict__ V, float* __restrict__ O)
{
    extern __shared__ float smf[];
    float* Kb = smf;                       // [2][64][68]
    float* Vb = Kb + 2 * 64 * KST;         // [2][64][72]

    const int tid  = threadIdx.x;
    const int warp = tid >> 5;
    const int lane = tid & 31;
    const int g  = lane >> 2;
    const int t4 = lane & 3;
    const int mrow = warp * 16;

    const int q0 = blockIdx.x << 6;
    const int h  = blockIdx.y;
    const int b  = blockIdx.z;

    const float* Qg = Q + ((size_t)(b * SS + q0)) * DD + h * HD;
    const float* Kg = K + ((size_t)b * SS) * DD + h * HD;
    const float* Vg = V + ((size_t)b * SS) * DD + h * HD;

    const uint32_t kb_b = (uint32_t)__cvta_generic_to_shared(Kb);
    const uint32_t vb_b = (uint32_t)__cvta_generic_to_shared(Vb);

    auto issue_kv = [&](int j) {
        int s = j & 1;
#pragma unroll
        for (int p = 0; p < 8; p++) {
            int idx = tid + p * 128;
            int r  = idx >> 4;
            int c  = (idx & 15) << 2;
            cp_async16(kb_b + (uint32_t)(s * 64 * KST + r * KST + c) * 4u,
                       Kg + (size_t)(j * 64 + r) * DD + c);
            cp_async16(vb_b + (uint32_t)(s * 64 * VST + r * VST + c) * 4u,
                       Vg + (size_t)(j * 64 + r) * DD + c);
        }
    };

#pragma unroll
    for (int p = 0; p < 8; p++) {
        int idx = tid + p * 128;
        int r  = idx >> 4;
        int c  = (idx & 15) << 2;
        cp_async16(kb_b + (uint32_t)(r * KST + c) * 4u,
                   Qg + (size_t)r * DD + c);
    }
    cp_commit();
    cp_wait<0>();
    __syncthreads();

    uint32_t qf[8][4];
#pragma unroll
    for (int ks = 0; ks < 8; ks++) {
        int cb = ks * 8 + t4;
        qf[ks][0] = __float_as_uint(Kb[(mrow + g)     * KST + cb]);
        qf[ks][1] = __float_as_uint(Kb[(mrow + g + 8) * KST + cb]);
        qf[ks][2] = __float_as_uint(Kb[(mrow + g)     * KST + cb + 4]);
        qf[ks][3] = __float_as_uint(Kb[(mrow + g + 8) * KST + cb + 4]);
    }
    __syncthreads();   // all warps done reading Q before K0 overwrites it

    issue_kv(0); cp_commit();
    issue_kv(1); cp_commit();
    cp_wait<1>();
    __syncthreads();

    float o_acc[8][4];
#pragma unroll
    for (int nt = 0; nt < 8; nt++)
#pragma unroll
        for (int c = 0; c < 4; c++) o_acc[nt][c] = 0.f;
    float m0r = -__int_as_float(0x7f800000);
    float m1r = -__int_as_float(0x7f800000);
    float l0r = 0.f, l1r = 0.f;

    const int srcA = (lane & 28) | (t4 >> 1);
    const int srcB = srcA + 2;
    const bool sel = (t4 & 1) != 0;

    for (int j = 0; j < SS / 64; j++) {
        const float* Kt = Kb + (j & 1) * 64 * KST;
        const float* Vt = Vb + (j & 1) * 64 * VST;

        float s[8][4];
#pragma unroll
        for (int nt = 0; nt < 8; nt++)
#pragma unroll
            for (int c = 0; c < 4; c++) s[nt][c] = 0.f;

        uint32_t kfA[8][2], kfB[8][2];
        {
            const int cb0 = t4;
#pragma unroll
            for (int nt = 0; nt < 8; nt++) {
                kfA[nt][0] = __float_as_uint(Kt[(nt * 8 + g) * KST + cb0]);
                kfA[nt][1] = __float_as_uint(Kt[(nt * 8 + g) * KST + cb0 + 4]);
            }
        }
#pragma unroll
        for (int ks = 0; ks < 8; ks++) {
            uint32_t (*cur)[2] = (ks & 1) ? kfB : kfA;
            uint32_t (*nxt)[2] = (ks & 1) ? kfA : kfB;
            if (ks < 7) {
                const int cb = (ks + 1) * 8 + t4;
#pragma unroll
                for (int nt = 0; nt < 8; nt++) {
                    nxt[nt][0] = __float_as_uint(Kt[(nt * 8 + g) * KST + cb]);
                    nxt[nt][1] = __float_as_uint(Kt[(nt * 8 + g) * KST + cb + 4]);
                }
            }
#pragma unroll
            for (int nt = 0; nt < 8; nt++)
                mma_tf32(s[nt], qf[ks], cur[nt]);
        }

        float mx0 = s[0][0], mx1 = s[0][2];
#pragma unroll
        for (int nt = 0; nt < 8; nt++) {
            mx0 = fmaxf(mx0, fmaxf(s[nt][0], s[nt][1]));
            mx1 = fmaxf(mx1, fmaxf(s[nt][2], s[nt][3]));
        }
        mx0 = fmaxf(mx0, __shfl_xor_sync(0xffffffffu, mx0, 1));
        mx0 = fmaxf(mx0, __shfl_xor_sync(0xffffffffu, mx0, 2));
        mx1 = fmaxf(mx1, __shfl_xor_sync(0xffffffffu, mx1, 1));
        mx1 = fmaxf(mx1, __shfl_xor_sync(0xffffffffu, mx1, 2));

        float mn0 = fmaxf(m0r, mx0);
        float mn1 = fmaxf(m1r, mx1);
        float corr0 = __expf(m0r - mn0);
        float corr1 = __expf(m1r - mn1);
        m0r = mn0; m1r = mn1;

        float rs0 = 0.f, rs1 = 0.f;
#pragma unroll
        for (int nt = 0; nt < 8; nt++) {
            s[nt][0] = __expf(s[nt][0] - mn0);
            s[nt][1] = __expf(s[nt][1] - mn0);
            s[nt][2] = __expf(s[nt][2] - mn1);
            s[nt][3] = __expf(s[nt][3] - mn1);
            rs0 += s[nt][0] + s[nt][1];
            rs1 += s[nt][2] + s[nt][3];
        }
        rs0 += __shfl_xor_sync(0xffffffffu, rs0, 1);
        rs0 += __shfl_xor_sync(0xffffffffu, rs0, 2);
        rs1 += __shfl_xor_sync(0xffffffffu, rs1, 1);
        rs1 += __shfl_xor_sync(0xffffffffu, rs1, 2);
        l0r = l0r * corr0 + rs0;
        l1r = l1r * corr1 + rs1;

#pragma unroll
        for (int nt = 0; nt < 8; nt++) {
            o_acc[nt][0] *= corr0; o_acc[nt][1] *= corr0;
            o_acc[nt][2] *= corr1; o_acc[nt][3] *= corr1;
        }

        auto build_af = [&](int ks, uint32_t af[4]) {
            float xA0 = __shfl_sync(0xffffffffu, s[ks][0], srcA);
            float xA1 = __shfl_sync(0xffffffffu, s[ks][1], srcA);
            float xA2 = __shfl_sync(0xffffffffu, s[ks][2], srcA);
            float xA3 = __shfl_sync(0xffffffffu, s[ks][3], srcA);
            float xB0 = __shfl_sync(0xffffffffu, s[ks][0], srcB);
            float xB1 = __shfl_sync(0xffffffffu, s[ks][1], srcB);
            float xB2 = __shfl_sync(0xffffffffu, s[ks][2], srcB);
            float xB3 = __shfl_sync(0xffffffffu, s[ks][3], srcB);
            af[0] = __float_as_uint(tf32r(sel ? xA1 : xA0));
            af[1] = __float_as_uint(tf32r(sel ? xA3 : xA2));
            af[2] = __float_as_uint(tf32r(sel ? xB1 : xB0));
            af[3] = __float_as_uint(tf32r(sel ? xB3 : xB2));
        };
        auto load_vf = [&](int ks, uint32_t vf[8][2]) {
#pragma unroll
            for (int nt = 0; nt < 8; nt++) {
                vf[nt][0] = __float_as_uint(Vt[(ks * 8 + t4)     * VST + nt * 8 + g]);
                vf[nt][1] = __float_as_uint(Vt[(ks * 8 + t4 + 4) * VST + nt * 8 + g]);
            }
        };

        uint32_t pfA[4], pfB[4], vfA[8][2], vfB[8][2];
        build_af(0, pfA);
        load_vf(0, vfA);
#pragma unroll
        for (int ks = 0; ks < 8; ks++) {
            uint32_t* pc = (ks & 1) ? pfB : pfA;
            uint32_t (*vc)[2] = (ks & 1) ? vfB : vfA;
            uint32_t* pn = (ks & 1) ? pfA : pfB;
            uint32_t (*vn)[2] = (ks & 1) ? vfA : vfB;
            if (ks < 7) {
                build_af(ks + 1, pn);
                load_vf(ks + 1, vn);
            }
#pragma unroll
            for (int nt = 0; nt < 8; nt++)
                mma_tf32(o_acc[nt], pc, vc[nt]);
        }

        __syncthreads();
        if (j + 2 < SS / 64) issue_kv(j + 2);
        cp_commit();
        cp_wait<1>();
        __syncthreads();
    }

    float inv0 = 1.0f / l0r;
    float inv1 = 1.0f / l1r;
    int row0 = q0 + mrow + g;
#pragma unroll
    for (int nt = 0; nt < 8; nt++) {
        int col = h * HD + nt * 8 + t4 * 2;
        float2 v0 = make_float2(tf32r(o_acc[nt][0] * inv0), tf32r(o_acc[nt][1] * inv0));
        float2 v1 = make_float2(tf32r(o_acc[nt][2] * inv1), tf32r(o_acc[nt][3] * inv1));
        *(float2*)(O + ((size_t)(b * SS + row0)) * DD + col)     = v0;
        *(float2*)(O + ((size_t)(b * SS + row0 + 8)) * DD + col) = v1;
    }
}

// ---------------------------------------------------------------------------
// Launch
// ---------------------------------------------------------------------------
extern "C" void kernel_launch(void* const* d_in, const int* in_sizes, int n_in,
                              void* d_out, int out_size)
{
    const float* q  = (const float*)d_in[0];
    const float* k  = (const float*)d_in[1];
    const float* v  = (const float*)d_in[2];
    const float* Wq = (const float*)d_in[3];
    const float* bq = (const float*)d_in[4];
    const float* Wk = (const float*)d_in[5];
    const float* bk = (const float*)d_in[6];
    const float* Wv = (const float*)d_in[7];
    const float* bv = (const float*)d_in[8];
    const float* Wo = (const float*)d_in[9];
    const float* bo = (const float*)d_in[10];
    float* out = (float*)d_out;

    float *qp, *kp, *vp, *att;
    cudaGetSymbolAddress((void**)&qp,  g_qp);
    cudaGetSymbolAddress((void**)&kp,  g_kp);
    cudaGetSymbolAddress((void**)&vp,  g_vp);
    cudaGetSymbolAddress((void**)&att, g_att);

    cudaFuncSetAttribute(gemm_qkv, cudaFuncAttributeMaxDynamicSharedMemorySize, GEMM_SMEM_BYTES);
    cudaFuncSetAttribute(gemm_o,   cudaFuncAttributeMaxDynamicSharedMemorySize, GEMM_SMEM_BYTES);
    cudaFuncSetAttribute(flash_tf32_pipe, cudaFuncAttributeMaxDynamicSharedMemorySize, FLASH_SMEM_BYTES);

    // 1) Q/K/V projections (raw inputs; fragment rounding in-loop; Q pre-scaled)
    dim3 qkv_grid(DD / 128, MM / 128, 3);   // (8, 32, 3)
    gemm_qkv<<<qkv_grid, 256, GEMM_SMEM_BYTES>>>(q, k, v, Wq, Wk, Wv,
                                                 bq, bk, bv, qp, kp, vp);

    // 2) Attention (BM=64: 1024 CTAs, 3 CTAs/SM)
    dim3 attn_grid(SS / 64, HH, BB);        // (32, 16, 2)
    flash_tf32_pipe<<<attn_grid, 128, FLASH_SMEM_BYTES>>>(qp, kp, vp, att);

    // 3) Output projection (A pre-rounded, W rounded in-loop; raw fp32 out)
    dim3 gemm_grid(DD / 128, MM / 128);     // (8, 32)
    gemm_o<<<gemm_grid, 256, GEMM_SMEM_BYTES>>>(att, Wo, bo, out);
}